// round 1
// baseline (speedup 1.0000x reference)
#include <cuda_runtime.h>
#include <cuda_bf16.h>
#include <cstdint>

// Problem: out[b,t,o] = (cummean_t x)[b,t,:] . W[t,:,o]
// B=4, T=1024, D=256, O=256. x:(B,T,D) f32, W:(T,D,O) f32, out:(B,T,O) f32.

#define BB 4
#define TT 1024
#define DD 256
#define OO 256

#define NSEG 32
#define SEGLEN 32   // NSEG*SEGLEN == TT

// scratch (device globals; no allocation allowed)
__device__ float g_segsum[BB * NSEG * DD];      // 128 KB
__device__ float g_cm[BB * TT * DD];            // 4 MB cumulative mean

// ---------------------------------------------------------------------------
// Kernel 1: per-segment sums. grid = B*NSEG blocks, 256 threads (one per d).
// ---------------------------------------------------------------------------
__global__ void k_segsum(const float* __restrict__ x) {
    int b = blockIdx.x / NSEG;
    int s = blockIdx.x % NSEG;
    int d = threadIdx.x;

    const float* xp = x + ((size_t)(b * TT + s * SEGLEN) * DD + d);
    float sum = 0.f;
#pragma unroll
    for (int i = 0; i < SEGLEN; ++i)
        sum += xp[(size_t)i * DD];
    g_segsum[(b * NSEG + s) * DD + d] = sum;
}

// ---------------------------------------------------------------------------
// Kernel 2: cumulative mean. grid = B*NSEG blocks, 256 threads (one per d).
// offset = sum of preceding segment sums, then serial scan within segment.
// ---------------------------------------------------------------------------
__global__ void k_cummean(const float* __restrict__ x) {
    int b = blockIdx.x / NSEG;
    int s = blockIdx.x % NSEG;
    int d = threadIdx.x;

    float offset = 0.f;
    const float* ss = g_segsum + b * NSEG * DD + d;
    for (int sp = 0; sp < s; ++sp)
        offset += ss[sp * DD];

    const float* xp = x + ((size_t)(b * TT + s * SEGLEN) * DD + d);
    float* cp = g_cm + ((size_t)(b * TT + s * SEGLEN) * DD + d);

    float run = offset;
#pragma unroll
    for (int i = 0; i < SEGLEN; ++i) {
        run += xp[(size_t)i * DD];
        int t = s * SEGLEN + i;
        cp[(size_t)i * DD] = run * (1.0f / (float)(t + 1));
    }
}

// ---------------------------------------------------------------------------
// Kernel 3: per-position GEMM, streaming W exactly once.
// grid = T/4 blocks, 256 threads. Thread layout: tg = tid>>6 selects one of
// 4 t-values in this block, o4 = tid&63 selects a float4 column of O.
// Each thread loops all 256 d: 1x LDG.128 of W + 16 FFMA per iteration.
// ---------------------------------------------------------------------------
__global__ __launch_bounds__(256) void k_gemm(const float* __restrict__ W,
                                              float* __restrict__ out) {
    __shared__ float cm_s[4][BB][DD];   // [t-group][b][d], 16 KB

    int tid = threadIdx.x;
    int t0 = blockIdx.x * 4;
    int tg = tid >> 6;        // 0..3
    int o4 = tid & 63;        // float4 column
    int t = t0 + tg;

    // cooperative load of cm for 4 t's x 4 b x 256 d (coalesced in d)
#pragma unroll
    for (int idx = tid; idx < 4 * BB * DD; idx += 256) {
        int tg_ = idx >> 10;
        int b = (idx >> 8) & 3;
        int d = idx & 255;
        cm_s[tg_][b][d] = g_cm[((size_t)(b * TT + t0 + tg_) * DD) + d];
    }
    __syncthreads();

    const float4* Wp = reinterpret_cast<const float4*>(W) +
                       ((size_t)t * DD) * (OO / 4) + o4;

    float4 a0 = {0.f, 0.f, 0.f, 0.f};
    float4 a1 = {0.f, 0.f, 0.f, 0.f};
    float4 a2 = {0.f, 0.f, 0.f, 0.f};
    float4 a3 = {0.f, 0.f, 0.f, 0.f};

#pragma unroll 8
    for (int d = 0; d < DD; ++d) {
        float4 w = Wp[(size_t)d * (OO / 4)];
        float c0 = cm_s[tg][0][d];
        float c1 = cm_s[tg][1][d];
        float c2 = cm_s[tg][2][d];
        float c3 = cm_s[tg][3][d];
        a0.x = fmaf(c0, w.x, a0.x); a0.y = fmaf(c0, w.y, a0.y);
        a0.z = fmaf(c0, w.z, a0.z); a0.w = fmaf(c0, w.w, a0.w);
        a1.x = fmaf(c1, w.x, a1.x); a1.y = fmaf(c1, w.y, a1.y);
        a1.z = fmaf(c1, w.z, a1.z); a1.w = fmaf(c1, w.w, a1.w);
        a2.x = fmaf(c2, w.x, a2.x); a2.y = fmaf(c2, w.y, a2.y);
        a2.z = fmaf(c2, w.z, a2.z); a2.w = fmaf(c2, w.w, a2.w);
        a3.x = fmaf(c3, w.x, a3.x); a3.y = fmaf(c3, w.y, a3.y);
        a3.z = fmaf(c3, w.z, a3.z); a3.w = fmaf(c3, w.w, a3.w);
    }

    float4* op = reinterpret_cast<float4*>(out);
    // out index (b, t, o): b*T*O + t*O + o4*4  -> float4 index /4
    op[((size_t)(0 * TT + t) * OO) / 4 + o4] = a0;
    op[((size_t)(1 * TT + t) * OO) / 4 + o4] = a1;
    op[((size_t)(2 * TT + t) * OO) / 4 + o4] = a2;
    op[((size_t)(3 * TT + t) * OO) / 4 + o4] = a3;
}

extern "C" void kernel_launch(void* const* d_in, const int* in_sizes, int n_in,
                              void* d_out, int out_size) {
    const float* x = (const float*)d_in[0];   // (B,T,D)
    const float* W = (const float*)d_in[1];   // (T,D,O)
    float* out = (float*)d_out;               // (B,T,O)

    k_segsum<<<BB * NSEG, DD>>>(x);
    k_cummean<<<BB * NSEG, DD>>>(x);
    k_gemm<<<TT / 4, 256>>>(W, out);
}

// round 3
// speedup vs baseline: 1.0041x; 1.0041x over previous
#include <cuda_runtime.h>
#include <cuda_bf16.h>
#include <cstdint>

// out[b,t,o] = (cummean_t x)[b,t,:] . W[t,:,o]
// B=4, T=1024, D=256, O=256. All fp32.

#define BB 4
#define TT 1024
#define DD 256
#define OO 256

#define NSEG 64
#define SEGLEN 16   // NSEG*SEGLEN == TT

__device__ float g_segsum[BB * NSEG * DD];      // 256 KB
__device__ float g_cm[BB * TT * DD];            // 4 MB cumulative mean

// ---------------------------------------------------------------------------
// Kernel 1: per-segment sums. grid = B*NSEG = 256 blocks, 64 threads (d4).
// ---------------------------------------------------------------------------
__global__ void k_segsum(const float* __restrict__ x) {
    int b = blockIdx.x / NSEG;
    int s = blockIdx.x % NSEG;
    int d4 = threadIdx.x;   // 0..63

    const float4* xp = reinterpret_cast<const float4*>(x) +
                       (size_t)(b * TT + s * SEGLEN) * (DD / 4) + d4;
    float4 sum = make_float4(0.f, 0.f, 0.f, 0.f);
#pragma unroll
    for (int i = 0; i < SEGLEN; ++i) {
        float4 v = xp[(size_t)i * (DD / 4)];
        sum.x += v.x; sum.y += v.y; sum.z += v.z; sum.w += v.w;
    }
    reinterpret_cast<float4*>(g_segsum)[(size_t)(b * NSEG + s) * (DD / 4) + d4] = sum;
}

// ---------------------------------------------------------------------------
// Kernel 2: cumulative mean. Prefix over prior segment sums + in-segment scan.
// ---------------------------------------------------------------------------
__global__ void k_cummean(const float* __restrict__ x) {
    int b = blockIdx.x / NSEG;
    int s = blockIdx.x % NSEG;
    int d4 = threadIdx.x;

    float4 run = make_float4(0.f, 0.f, 0.f, 0.f);
    const float4* ss = reinterpret_cast<const float4*>(g_segsum) +
                       (size_t)b * NSEG * (DD / 4) + d4;
    for (int sp = 0; sp < s; ++sp) {
        float4 v = ss[(size_t)sp * (DD / 4)];
        run.x += v.x; run.y += v.y; run.z += v.z; run.w += v.w;
    }

    const float4* xp = reinterpret_cast<const float4*>(x) +
                       (size_t)(b * TT + s * SEGLEN) * (DD / 4) + d4;
    float4* cp = reinterpret_cast<float4*>(g_cm) +
                 (size_t)(b * TT + s * SEGLEN) * (DD / 4) + d4;

#pragma unroll
    for (int i = 0; i < SEGLEN; ++i) {
        float4 v = xp[(size_t)i * (DD / 4)];
        run.x += v.x; run.y += v.y; run.z += v.z; run.w += v.w;
        float inv = 1.0f / (float)(s * SEGLEN + i + 1);
        float4 o;
        o.x = run.x * inv; o.y = run.y * inv; o.z = run.z * inv; o.w = run.w * inv;
        cp[(size_t)i * (DD / 4)] = o;
    }
}

// ---------------------------------------------------------------------------
// Kernel 3: per-position GEMM, streaming W exactly once.
// grid = T/2 = 512 blocks, 128 threads -> whole grid resident in one wave.
// ---------------------------------------------------------------------------
__device__ __forceinline__ void fma4(float4& acc, float s, const float4& v) {
    acc.x = fmaf(s, v.x, acc.x);
    acc.y = fmaf(s, v.y, acc.y);
    acc.z = fmaf(s, v.z, acc.z);
    acc.w = fmaf(s, v.w, acc.w);
}

__global__ __launch_bounds__(128) void k_gemm(const float* __restrict__ W,
                                              float* __restrict__ out) {
    __shared__ float4 cm_s[2][BB][DD / 4];   // 8 KB

    int tid = threadIdx.x;
    int t0 = blockIdx.x * 2;
    int tg = tid >> 6;        // 0..1
    int o4 = tid & 63;        // float4 O-column
    int t = t0 + tg;

    // cooperative load: 2 t's x 4 b x 64 float4 = 512 float4, 4 per thread
    const float4* cm_g = reinterpret_cast<const float4*>(g_cm);
#pragma unroll
    for (int k = 0; k < 4; ++k) {
        int idx = tid + k * 128;
        int tg_ = idx >> 8;
        int b   = (idx >> 6) & 3;
        int d4_ = idx & 63;
        cm_s[tg_][b][d4_] = cm_g[(size_t)(b * TT + t0 + tg_) * (DD / 4) + d4_];
    }
    __syncthreads();

    const float4* W4 = reinterpret_cast<const float4*>(W) +
                       (size_t)t * DD * (OO / 4) + o4;

    float4 a0 = make_float4(0.f, 0.f, 0.f, 0.f);
    float4 a1 = make_float4(0.f, 0.f, 0.f, 0.f);
    float4 a2 = make_float4(0.f, 0.f, 0.f, 0.f);
    float4 a3 = make_float4(0.f, 0.f, 0.f, 0.f);

#pragma unroll 2
    for (int d4 = 0; d4 < DD / 4; ++d4) {
        float4 w0 = W4[(size_t)(4 * d4 + 0) * (OO / 4)];
        float4 w1 = W4[(size_t)(4 * d4 + 1) * (OO / 4)];
        float4 w2 = W4[(size_t)(4 * d4 + 2) * (OO / 4)];
        float4 w3 = W4[(size_t)(4 * d4 + 3) * (OO / 4)];

        float4 c;
        c = cm_s[tg][0][d4];
        fma4(a0, c.x, w0); fma4(a0, c.y, w1); fma4(a0, c.z, w2); fma4(a0, c.w, w3);
        c = cm_s[tg][1][d4];
        fma4(a1, c.x, w0); fma4(a1, c.y, w1); fma4(a1, c.z, w2); fma4(a1, c.w, w3);
        c = cm_s[tg][2][d4];
        fma4(a2, c.x, w0); fma4(a2, c.y, w1); fma4(a2, c.z, w2); fma4(a2, c.w, w3);
        c = cm_s[tg][3][d4];
        fma4(a3, c.x, w0); fma4(a3, c.y, w1); fma4(a3, c.z, w2); fma4(a3, c.w, w3);
    }

    float4* op = reinterpret_cast<float4*>(out);
    op[(size_t)(0 * TT + t) * (OO / 4) + o4] = a0;
    op[(size_t)(1 * TT + t) * (OO / 4) + o4] = a1;
    op[(size_t)(2 * TT + t) * (OO / 4) + o4] = a2;
    op[(size_t)(3 * TT + t) * (OO / 4) + o4] = a3;
}

extern "C" void kernel_launch(void* const* d_in, const int* in_sizes, int n_in,
                              void* d_out, int out_size) {
    const float* x = (const float*)d_in[0];   // (B,T,D)
    const float* W = (const float*)d_in[1];   // (T,D,O)
    float* out = (float*)d_out;               // (B,T,O)

    k_segsum<<<BB * NSEG, 64>>>(x);
    k_cummean<<<BB * NSEG, 64>>>(x);
    k_gemm<<<TT / 2, 128>>>(W, out);
}

// round 4
// speedup vs baseline: 1.2141x; 1.2092x over previous
#include <cuda_runtime.h>
#include <cuda_bf16.h>
#include <cstdint>

// out[b,t,o] = (cummean_t x)[b,t,:] . W[t,:,o]
// B=4, T=1024, D=256, O=256. All fp32.

#define BB 4
#define TT 1024
#define DD 256
#define OO 256

#define NSEG 64
#define SEGLEN 16   // NSEG*SEGLEN == TT

#define STAGES 4
#define DCHUNK 4                 // d-rows per stage
#define NCHUNK (DD / DCHUNK)     // 64

__device__ float g_segsum[BB * NSEG * DD];      // 256 KB
__device__ float g_cm[BB * TT * DD];            // 4 MB cumulative mean

// ---------------------------------------------------------------------------
// Kernel 1: per-segment sums. grid = B*NSEG = 256 blocks, 64 threads (d4).
// ---------------------------------------------------------------------------
__global__ void k_segsum(const float* __restrict__ x) {
    int b = blockIdx.x / NSEG;
    int s = blockIdx.x % NSEG;
    int d4 = threadIdx.x;   // 0..63

    const float4* xp = reinterpret_cast<const float4*>(x) +
                       (size_t)(b * TT + s * SEGLEN) * (DD / 4) + d4;
    float4 sum = make_float4(0.f, 0.f, 0.f, 0.f);
#pragma unroll
    for (int i = 0; i < SEGLEN; ++i) {
        float4 v = xp[(size_t)i * (DD / 4)];
        sum.x += v.x; sum.y += v.y; sum.z += v.z; sum.w += v.w;
    }
    reinterpret_cast<float4*>(g_segsum)[(size_t)(b * NSEG + s) * (DD / 4) + d4] = sum;
}

// ---------------------------------------------------------------------------
// Kernel 2: cumulative mean. Prefix over prior segment sums (4-way ILP) then
// in-segment serial scan, all float4.
// ---------------------------------------------------------------------------
__global__ void k_cummean(const float* __restrict__ x) {
    int b = blockIdx.x / NSEG;
    int s = blockIdx.x % NSEG;
    int d4 = threadIdx.x;

    const float4* ss = reinterpret_cast<const float4*>(g_segsum) +
                       (size_t)b * NSEG * (DD / 4) + d4;

    float4 r0 = make_float4(0.f, 0.f, 0.f, 0.f);
    float4 r1 = r0, r2 = r0, r3 = r0;
    int sp = 0;
    for (; sp + 4 <= s; sp += 4) {
        float4 v0 = ss[(size_t)(sp + 0) * (DD / 4)];
        float4 v1 = ss[(size_t)(sp + 1) * (DD / 4)];
        float4 v2 = ss[(size_t)(sp + 2) * (DD / 4)];
        float4 v3 = ss[(size_t)(sp + 3) * (DD / 4)];
        r0.x += v0.x; r0.y += v0.y; r0.z += v0.z; r0.w += v0.w;
        r1.x += v1.x; r1.y += v1.y; r1.z += v1.z; r1.w += v1.w;
        r2.x += v2.x; r2.y += v2.y; r2.z += v2.z; r2.w += v2.w;
        r3.x += v3.x; r3.y += v3.y; r3.z += v3.z; r3.w += v3.w;
    }
    for (; sp < s; ++sp) {
        float4 v = ss[(size_t)sp * (DD / 4)];
        r0.x += v.x; r0.y += v.y; r0.z += v.z; r0.w += v.w;
    }
    float4 run;
    run.x = (r0.x + r1.x) + (r2.x + r3.x);
    run.y = (r0.y + r1.y) + (r2.y + r3.y);
    run.z = (r0.z + r1.z) + (r2.z + r3.z);
    run.w = (r0.w + r1.w) + (r2.w + r3.w);

    const float4* xp = reinterpret_cast<const float4*>(x) +
                       (size_t)(b * TT + s * SEGLEN) * (DD / 4) + d4;
    float4* cp = reinterpret_cast<float4*>(g_cm) +
                 (size_t)(b * TT + s * SEGLEN) * (DD / 4) + d4;

#pragma unroll
    for (int i = 0; i < SEGLEN; ++i) {
        float4 v = xp[(size_t)i * (DD / 4)];
        run.x += v.x; run.y += v.y; run.z += v.z; run.w += v.w;
        float inv = 1.0f / (float)(s * SEGLEN + i + 1);
        float4 o;
        o.x = run.x * inv; o.y = run.y * inv; o.z = run.z * inv; o.w = run.w * inv;
        cp[(size_t)i * (DD / 4)] = o;
    }
}

// ---------------------------------------------------------------------------
// Kernel 3: GEMM with cp.async 4-stage pipeline streaming W through smem.
// grid = T/2 = 512 blocks, 128 threads. tg = tid>>6 selects t, o4 = tid&63
// selects a float4 O-column. Stage = 4 d-rows x 2 t x 1KB = 8 KB.
// ---------------------------------------------------------------------------
__device__ __forceinline__ void fma4(float4& acc, float s, const float4& v) {
    acc.x = fmaf(s, v.x, acc.x);
    acc.y = fmaf(s, v.y, acc.y);
    acc.z = fmaf(s, v.z, acc.z);
    acc.w = fmaf(s, v.w, acc.w);
}

__device__ __forceinline__ void cp16(void* smem_dst, const void* gmem_src) {
    uint32_t s = (uint32_t)__cvta_generic_to_shared(smem_dst);
    asm volatile("cp.async.cg.shared.global [%0], [%1], 16;\n"
                 :: "r"(s), "l"(gmem_src));
}

__global__ __launch_bounds__(128) void k_gemm(const float* __restrict__ W,
                                              float* __restrict__ out) {
    __shared__ float4 ws[STAGES][2][DCHUNK][OO / 4];  // 4*2*4*64*16 = 32 KB
    __shared__ float4 cm_s[2][BB][DD / 4];            // 8 KB

    int tid = threadIdx.x;
    int t0 = blockIdx.x * 2;
    int tg = tid >> 6;        // 0..1
    int o4 = tid & 63;        // float4 O-column

    const float4* W4 = reinterpret_cast<const float4*>(W);

    // issue one chunk's cp.asyncs into stage st
    auto issue = [&](int st, int ch) {
#pragma unroll
        for (int k = 0; k < 4; ++k) {
            int slot = tid + k * 128;          // 0..511
            int tg_ = slot >> 8;               // 0..1
            int dd  = (slot >> 6) & (DCHUNK - 1);
            int oo  = slot & 63;
            const float4* src = W4 + ((size_t)(t0 + tg_) * DD +
                                      (ch * DCHUNK + dd)) * (OO / 4) + oo;
            cp16(&ws[st][tg_][dd][oo], src);
        }
    };

    // prologue: fill first STAGES-1 stages
#pragma unroll
    for (int p = 0; p < STAGES - 1; ++p) {
        issue(p, p);
        asm volatile("cp.async.commit_group;\n" ::: "memory");
    }

    // cooperative cm load: 2 t x 4 b x 64 float4 = 512 float4
    const float4* cm_g = reinterpret_cast<const float4*>(g_cm);
#pragma unroll
    for (int k = 0; k < 4; ++k) {
        int idx = tid + k * 128;
        int tg_ = idx >> 8;
        int b   = (idx >> 6) & 3;
        int d4_ = idx & 63;
        cm_s[tg_][b][d4_] = cm_g[(size_t)(b * TT + t0 + tg_) * (DD / 4) + d4_];
    }
    __syncthreads();

    float4 a0 = make_float4(0.f, 0.f, 0.f, 0.f);
    float4 a1 = a0, a2 = a0, a3 = a0;

    for (int ch = 0; ch < NCHUNK; ++ch) {
        asm volatile("cp.async.wait_group %0;\n" :: "n"(STAGES - 2) : "memory");
        __syncthreads();

        int st = ch & (STAGES - 1);

        // cm for d-range [ch*4, ch*4+4) = one float4 per b
        float4 c0 = cm_s[tg][0][ch];
        float4 c1 = cm_s[tg][1][ch];
        float4 c2 = cm_s[tg][2][ch];
        float4 c3 = cm_s[tg][3][ch];

        {
            float4 w = ws[st][tg][0][o4];
            fma4(a0, c0.x, w); fma4(a1, c1.x, w); fma4(a2, c2.x, w); fma4(a3, c3.x, w);
        }
        {
            float4 w = ws[st][tg][1][o4];
            fma4(a0, c0.y, w); fma4(a1, c1.y, w); fma4(a2, c2.y, w); fma4(a3, c3.y, w);
        }
        {
            float4 w = ws[st][tg][2][o4];
            fma4(a0, c0.z, w); fma4(a1, c1.z, w); fma4(a2, c2.z, w); fma4(a3, c3.z, w);
        }
        {
            float4 w = ws[st][tg][3][o4];
            fma4(a0, c0.w, w); fma4(a1, c1.w, w); fma4(a2, c2.w, w); fma4(a3, c3.w, w);
        }

        __syncthreads();
        int nxt = ch + STAGES - 1;
        if (nxt < NCHUNK)
            issue(nxt & (STAGES - 1), nxt);
        // always commit (possibly-empty group) to keep wait_group bookkeeping exact
        asm volatile("cp.async.commit_group;\n" ::: "memory");
    }

    int t = t0 + tg;
    float4* op = reinterpret_cast<float4*>(out);
    op[(size_t)(0 * TT + t) * (OO / 4) + o4] = a0;
    op[(size_t)(1 * TT + t) * (OO / 4) + o4] = a1;
    op[(size_t)(2 * TT + t) * (OO / 4) + o4] = a2;
    op[(size_t)(3 * TT + t) * (OO / 4) + o4] = a3;
}

extern "C" void kernel_launch(void* const* d_in, const int* in_sizes, int n_in,
                              void* d_out, int out_size) {
    const float* x = (const float*)d_in[0];   // (B,T,D)
    const float* W = (const float*)d_in[1];   // (T,D,O)
    float* out = (float*)d_out;               // (B,T,O)

    k_segsum<<<BB * NSEG, 64>>>(x);
    k_cummean<<<BB * NSEG, 64>>>(x);
    k_gemm<<<TT / 2, 128>>>(W, out);
}

// round 5
// speedup vs baseline: 1.4521x; 1.1959x over previous
#include <cuda_runtime.h>
#include <cuda_bf16.h>
#include <cstdint>

// out[b,t,o] = (cummean_t x)[b,t,:] . W[t,:,o]
// B=4, T=1024, D=256, O=256. All fp32.

#define BB 4
#define TT 1024
#define DD 256
#define OO 256

#define NSEG 64
#define SEGLEN 16     // NSEG*SEGLEN == TT
#define QLEN 4        // quarter length; 4 quarters per segment

#define STAGES 4
#define DCHUNK 4                 // d-rows per stage
#define NCHUNK (DD / DCHUNK)     // 64

__device__ float g_segsum[BB * NSEG * DD];      // 256 KB (L2-resident)
__device__ float g_cm[BB * TT * DD];            // 4 MB cumulative mean

// ---------------------------------------------------------------------------
// Kernel 1: per-segment sums. grid = B*NSEG = 256 blocks, 256 threads.
// thread = (q = tid>>6, d4 = tid&63); each sums QLEN=4 t-rows, smem-reduce.
// ---------------------------------------------------------------------------
__global__ __launch_bounds__(256) void k_segsum(const float* __restrict__ x) {
    __shared__ float4 qs[4][64];

    int b = blockIdx.x / NSEG;
    int s = blockIdx.x % NSEG;
    int d4 = threadIdx.x & 63;
    int q  = threadIdx.x >> 6;

    const float4* xp = reinterpret_cast<const float4*>(x) +
                       (size_t)(b * TT + s * SEGLEN + q * QLEN) * (DD / 4) + d4;
    float4 sum = make_float4(0.f, 0.f, 0.f, 0.f);
#pragma unroll
    for (int i = 0; i < QLEN; ++i) {
        float4 v = xp[(size_t)i * (DD / 4)];
        sum.x += v.x; sum.y += v.y; sum.z += v.z; sum.w += v.w;
    }
    qs[q][d4] = sum;
    __syncthreads();

    if (q == 0) {
        float4 a = qs[0][d4], b1 = qs[1][d4], c = qs[2][d4], d = qs[3][d4];
        float4 r;
        r.x = (a.x + b1.x) + (c.x + d.x);
        r.y = (a.y + b1.y) + (c.y + d.y);
        r.z = (a.z + b1.z) + (c.z + d.z);
        r.w = (a.w + b1.w) + (c.w + d.w);
        reinterpret_cast<float4*>(g_segsum)[(size_t)(b * NSEG + s) * (DD / 4) + d4] = r;
    }
}

// ---------------------------------------------------------------------------
// Kernel 2: cumulative mean. grid = B*NSEG = 256 blocks, 256 threads.
// thread (q, d4): loads its 4 x rows, exchanges quarter sums in smem,
// prefixes prior segment sums (L2 hits), then scans its 4 t's.
// ---------------------------------------------------------------------------
__global__ __launch_bounds__(256) void k_cummean(const float* __restrict__ x) {
    __shared__ float4 qs[4][64];

    int b = blockIdx.x / NSEG;
    int s = blockIdx.x % NSEG;
    int d4 = threadIdx.x & 63;
    int q  = threadIdx.x >> 6;

    int tbase = s * SEGLEN + q * QLEN;
    const float4* xp = reinterpret_cast<const float4*>(x) +
                       (size_t)(b * TT + tbase) * (DD / 4) + d4;

    float4 v0 = xp[0 * (DD / 4)];
    float4 v1 = xp[1 * (DD / 4)];
    float4 v2 = xp[2 * (DD / 4)];
    float4 v3 = xp[3 * (DD / 4)];

    float4 qsum;
    qsum.x = (v0.x + v1.x) + (v2.x + v3.x);
    qsum.y = (v0.y + v1.y) + (v2.y + v3.y);
    qsum.z = (v0.z + v1.z) + (v2.z + v3.z);
    qsum.w = (v0.w + v1.w) + (v2.w + v3.w);
    qs[q][d4] = qsum;

    // prefix over prior segments (coalesced, L2-resident)
    const float4* ss = reinterpret_cast<const float4*>(g_segsum) +
                       (size_t)b * NSEG * (DD / 4) + d4;
    float4 r0 = make_float4(0.f, 0.f, 0.f, 0.f);
    float4 r1 = r0, r2 = r0, r3 = r0;
    int sp = 0;
    for (; sp + 4 <= s; sp += 4) {
        float4 a = ss[(size_t)(sp + 0) * (DD / 4)];
        float4 bb = ss[(size_t)(sp + 1) * (DD / 4)];
        float4 c = ss[(size_t)(sp + 2) * (DD / 4)];
        float4 d = ss[(size_t)(sp + 3) * (DD / 4)];
        r0.x += a.x;  r0.y += a.y;  r0.z += a.z;  r0.w += a.w;
        r1.x += bb.x; r1.y += bb.y; r1.z += bb.z; r1.w += bb.w;
        r2.x += c.x;  r2.y += c.y;  r2.z += c.z;  r2.w += c.w;
        r3.x += d.x;  r3.y += d.y;  r3.z += d.z;  r3.w += d.w;
    }
    for (; sp < s; ++sp) {
        float4 a = ss[(size_t)sp * (DD / 4)];
        r0.x += a.x; r0.y += a.y; r0.z += a.z; r0.w += a.w;
    }
    float4 run;
    run.x = (r0.x + r1.x) + (r2.x + r3.x);
    run.y = (r0.y + r1.y) + (r2.y + r3.y);
    run.z = (r0.z + r1.z) + (r2.z + r3.z);
    run.w = (r0.w + r1.w) + (r2.w + r3.w);

    __syncthreads();
    // add earlier quarters within this segment
#pragma unroll
    for (int qp = 0; qp < 3; ++qp) {
        if (qp < q) {
            float4 a = qs[qp][d4];
            run.x += a.x; run.y += a.y; run.z += a.z; run.w += a.w;
        }
    }

    float4* cp = reinterpret_cast<float4*>(g_cm) +
                 (size_t)(b * TT + tbase) * (DD / 4) + d4;
#pragma unroll
    for (int i = 0; i < QLEN; ++i) {
        float4 v = (i == 0) ? v0 : (i == 1) ? v1 : (i == 2) ? v2 : v3;
        run.x += v.x; run.y += v.y; run.z += v.z; run.w += v.w;
        float inv = 1.0f / (float)(tbase + i + 1);
        float4 o;
        o.x = run.x * inv; o.y = run.y * inv; o.z = run.z * inv; o.w = run.w * inv;
        cp[(size_t)i * (DD / 4)] = o;
    }
}

// ---------------------------------------------------------------------------
// Kernel 3: GEMM with cp.async 4-stage pipeline, 1 barrier per chunk.
// grid = T/2 = 512 blocks, 128 threads.
// ---------------------------------------------------------------------------
__device__ __forceinline__ void fma4(float4& acc, float s, const float4& v) {
    acc.x = fmaf(s, v.x, acc.x);
    acc.y = fmaf(s, v.y, acc.y);
    acc.z = fmaf(s, v.z, acc.z);
    acc.w = fmaf(s, v.w, acc.w);
}

__device__ __forceinline__ void cp16(void* smem_dst, const void* gmem_src) {
    uint32_t s = (uint32_t)__cvta_generic_to_shared(smem_dst);
    asm volatile("cp.async.cg.shared.global [%0], [%1], 16;\n"
                 :: "r"(s), "l"(gmem_src));
}

__global__ __launch_bounds__(128) void k_gemm(const float* __restrict__ W,
                                              float* __restrict__ out) {
    __shared__ float4 ws[STAGES][2][DCHUNK][OO / 4];  // 32 KB
    __shared__ float4 cm_s[2][BB][DD / 4];            // 8 KB

    int tid = threadIdx.x;
    int t0 = blockIdx.x * 2;
    int tg = tid >> 6;        // 0..1
    int o4 = tid & 63;        // float4 O-column

    const float4* W4 = reinterpret_cast<const float4*>(W);

    auto issue = [&](int st, int ch) {
#pragma unroll
        for (int k = 0; k < 4; ++k) {
            int slot = tid + k * 128;          // 0..511
            int tg_ = slot >> 8;
            int dd  = (slot >> 6) & (DCHUNK - 1);
            int oo  = slot & 63;
            const float4* src = W4 + ((size_t)(t0 + tg_) * DD +
                                      (ch * DCHUNK + dd)) * (OO / 4) + oo;
            cp16(&ws[st][tg_][dd][oo], src);
        }
    };

#pragma unroll
    for (int p = 0; p < STAGES - 1; ++p) {
        issue(p, p);
        asm volatile("cp.async.commit_group;\n" ::: "memory");
    }

    const float4* cm_g = reinterpret_cast<const float4*>(g_cm);
#pragma unroll
    for (int k = 0; k < 4; ++k) {
        int idx = tid + k * 128;
        int tg_ = idx >> 8;
        int b   = (idx >> 6) & 3;
        int d4_ = idx & 63;
        cm_s[tg_][b][d4_] = cm_g[(size_t)(b * TT + t0 + tg_) * (DD / 4) + d4_];
    }

    float4 a0 = make_float4(0.f, 0.f, 0.f, 0.f);
    float4 a1 = a0, a2 = a0, a3 = a0;

    for (int ch = 0; ch < NCHUNK; ++ch) {
        asm volatile("cp.async.wait_group %0;\n" :: "n"(STAGES - 2) : "memory");
        __syncthreads();

        int st = ch & (STAGES - 1);

        float4 c0 = cm_s[tg][0][ch];
        float4 c1 = cm_s[tg][1][ch];
        float4 c2 = cm_s[tg][2][ch];
        float4 c3 = cm_s[tg][3][ch];

        {
            float4 w = ws[st][tg][0][o4];
            fma4(a0, c0.x, w); fma4(a1, c1.x, w); fma4(a2, c2.x, w); fma4(a3, c3.x, w);
        }
        {
            float4 w = ws[st][tg][1][o4];
            fma4(a0, c0.y, w); fma4(a1, c1.y, w); fma4(a2, c2.y, w); fma4(a3, c3.y, w);
        }
        {
            float4 w = ws[st][tg][2][o4];
            fma4(a0, c0.z, w); fma4(a1, c1.z, w); fma4(a2, c2.z, w); fma4(a3, c3.z, w);
        }
        {
            float4 w = ws[st][tg][3][o4];
            fma4(a0, c0.w, w); fma4(a1, c1.w, w); fma4(a2, c2.w, w); fma4(a3, c3.w, w);
        }

        // Stage (ch+STAGES-1)%STAGES was last read in chunk ch-1; all threads
        // passed this chunk's barrier, so it is free to overwrite: no 2nd bar.
        int nxt = ch + STAGES - 1;
        if (nxt < NCHUNK)
            issue(nxt & (STAGES - 1), nxt);
        asm volatile("cp.async.commit_group;\n" ::: "memory");
    }

    int t = t0 + tg;
    float4* op = reinterpret_cast<float4*>(out);
    op[(size_t)(0 * TT + t) * (OO / 4) + o4] = a0;
    op[(size_t)(1 * TT + t) * (OO / 4) + o4] = a1;
    op[(size_t)(2 * TT + t) * (OO / 4) + o4] = a2;
    op[(size_t)(3 * TT + t) * (OO / 4) + o4] = a3;
}

extern "C" void kernel_launch(void* const* d_in, const int* in_sizes, int n_in,
                              void* d_out, int out_size) {
    const float* x = (const float*)d_in[0];   // (B,T,D)
    const float* W = (const float*)d_in[1];   // (T,D,O)
    float* out = (float*)d_out;               // (B,T,O)

    k_segsum<<<BB * NSEG, 256>>>(x);
    k_cummean<<<BB * NSEG, 256>>>(x);
    k_gemm<<<TT / 2, 128>>>(W, out);
}